// round 10
// baseline (speedup 1.0000x reference)
#include <cuda_runtime.h>
#include <cstdint>

#define TB      64
#define THREADS 256
#define HID     128
#define TSTEPS  28
#define INP     28
#define BATCH   8192
#define KA      156     // INP+HID concat k (layer 0)
#define KB      256     // HID+HID concat k (layer 1)
#define LDA     164     // activation row stride (floats), kernel A
#define LDB     260     // activation row stride, kernel B

// layer-0 output sequence, [t][b][h]
__device__ __align__(16) float g_out0[(size_t)TSTEPS * BATCH * HID];

typedef unsigned long long u64;

__device__ __forceinline__ u64 pack_dup(float a) {
    u64 r; asm("mov.b64 %0, {%1, %1};" : "=l"(r) : "r"(__float_as_uint(a))); return r;
}
__device__ __forceinline__ u64 pack_pair(float lo, float hi) {
    u64 r; asm("mov.b64 %0, {%1, %2};" : "=l"(r) : "r"(__float_as_uint(lo)), "r"(__float_as_uint(hi))); return r;
}
__device__ __forceinline__ void ffma2(u64& d, u64 a, u64 b) {
    asm("fma.rn.f32x2 %0, %1, %2, %0;" : "+l"(d) : "l"(a), "l"(b));
}
__device__ __forceinline__ float lo2(u64 v) { return __uint_as_float((unsigned)v); }
__device__ __forceinline__ float hi2(u64 v) { return __uint_as_float((unsigned)(v >> 32)); }

__device__ __forceinline__ float fast_tanh(float x) {
    float e = __expf(2.0f * x);
    return 1.0f - __fdividef(2.0f, e + 1.0f);
}

// bank-permuted weight column: thread jg's m-th float4 = [m*32+jg*4 .. +3]
__device__ __forceinline__ int wcol(int j) {
    int jg = j >> 4, m = (j >> 2) & 3, r = j & 3;
    return m * 32 + jg * 4 + r;
}

extern __shared__ float smem[];

// 2-row x 16-col register-tile step over concat-k, f32x2 accumulators.
#define GEMM_LOOP(KK)                                                          \
    _Pragma("unroll 4")                                                        \
    for (int k = 0; k < KK; ++k) {                                             \
        u64 A0 = pack_dup(a0p[k]), A1 = pack_dup(a1p[k]);                      \
        const float* wk = wp + k * HID;                                        \
        _Pragma("unroll")                                                      \
        for (int m = 0; m < 4; ++m) {                                          \
            ulonglong2 w = *reinterpret_cast<const ulonglong2*>(wk + m * 32);  \
            ffma2(acc[0][2*m], A0, w.x); ffma2(acc[0][2*m+1], A0, w.y);        \
            ffma2(acc[1][2*m], A1, w.x); ffma2(acc[1][2*m+1], A1, w.y);        \
        }                                                                      \
    }

// ---------------- layer 0: full sequence -> g_out0 ----------------
__global__ void __launch_bounds__(THREADS, 1)
rnn_layer0(const float* __restrict__ x,
           const float* __restrict__ Wih0, const float* __restrict__ Whh0,
           const float* __restrict__ bih0, const float* __restrict__ bhh0)
{
    float* Wre  = smem;                  // KA*HID
    float* Arow = Wre + KA * HID;        // TB*LDA: [b][0..27]=x_t, [28..155]=h
    float* b0s  = Arow + TB * LDA;       // HID

    const int tid = threadIdx.x;
    const int B0  = blockIdx.x * TB;

    for (int d = tid; d < KA * HID; d += THREADS) {
        int k = d >> 7, j = d & 127;
        Wre[k * HID + wcol(j)] = (k < INP) ? Wih0[j * INP + k]
                                           : Whh0[j * HID + (k - INP)];
    }
    for (int j = tid; j < HID; j += THREADS) b0s[j] = bih0[j] + bhh0[j];
    for (int d = tid; d < TB * HID; d += THREADS)
        Arow[(d >> 7) * LDA + INP + (d & 127)] = 0.0f;   // h0 = 0
    __syncthreads();

    const int jg = tid & 7, bg = tid >> 3;   // 8 j-groups x 32 b-groups
    const int j0 = jg * 16, b0 = bg * 2;
    const float* a0p = &Arow[(b0 + 0) * LDA];
    const float* a1p = &Arow[(b0 + 1) * LDA];
    const float* wp  = &Wre[jg * 4];

    for (int t = 0; t < TSTEPS; ++t) {
        for (int e = tid; e < TB * INP; e += THREADS) {       // stage x[:,t,:]
            int b = e / INP, i = e - b * INP;
            Arow[b * LDA + i] = x[(size_t)(B0 + b) * (TSTEPS * INP) + t * INP + i];
        }
        __syncthreads();   // x staged + prev-step h writes visible

        u64 acc[2][8];
        #pragma unroll
        for (int jp = 0; jp < 8; ++jp) {
            u64 bb = pack_pair(b0s[j0 + 2*jp], b0s[j0 + 2*jp + 1]);
            acc[0][jp] = bb; acc[1][jp] = bb;
        }
        GEMM_LOOP(KA)
        __syncthreads();   // all reads of h done before overwrite

        #pragma unroll
        for (int bi = 0; bi < 2; ++bi) {
            float v[16];
            #pragma unroll
            for (int jp = 0; jp < 8; ++jp) {
                v[2*jp]   = fast_tanh(lo2(acc[bi][jp]));
                v[2*jp+1] = fast_tanh(hi2(acc[bi][jp]));
            }
            float* dA = &Arow[(b0 + bi) * LDA + INP + j0];
            float* dG = &g_out0[((size_t)t * BATCH + B0 + b0 + bi) * HID + j0];
            #pragma unroll
            for (int m = 0; m < 4; ++m) {
                float4 f = make_float4(v[4*m], v[4*m+1], v[4*m+2], v[4*m+3]);
                *reinterpret_cast<float4*>(dA + 4*m) = f;
                *reinterpret_cast<float4*>(dG + 4*m) = f;
            }
        }
        // next pre-GEMM __syncthreads orders these h writes for all readers
    }
}

// ---------------- layer 1 + FC head ----------------
__global__ void __launch_bounds__(THREADS, 1)
rnn_layer1_fc(const float* __restrict__ Wih1, const float* __restrict__ Whh1,
              const float* __restrict__ bih1, const float* __restrict__ bhh1,
              const float* __restrict__ fcw,  const float* __restrict__ fcb,
              float* __restrict__ out)
{
    float* Wre  = smem;                   // KB*HID
    float* Arow = Wre + KB * HID;         // TB*LDB: [0..127]=in0, [128..255]=h1
    float* b1s  = Arow + TB * LDB;        // HID
    float* fcs  = b1s + HID;              // 10*HID
    float* fcbs = fcs + 10 * HID;         // 16

    const int tid = threadIdx.x;
    const int B0  = blockIdx.x * TB;

    for (int d = tid; d < KB * HID; d += THREADS) {
        int k = d >> 7, j = d & 127;
        Wre[k * HID + wcol(j)] = (k < HID) ? Wih1[j * HID + k]
                                           : Whh1[j * HID + (k - HID)];
    }
    for (int j = tid; j < HID; j += THREADS) b1s[j] = bih1[j] + bhh1[j];
    for (int d = tid; d < 10 * HID; d += THREADS) fcs[d] = fcw[d];
    if (tid < 10) fcbs[tid] = fcb[tid];
    for (int d = tid; d < TB * HID; d += THREADS)
        Arow[(d >> 7) * LDB + HID + (d & 127)] = 0.0f;   // h0 = 0
    __syncthreads();

    const int jg = tid & 7, bg = tid >> 3;
    const int j0 = jg * 16, b0 = bg * 2;
    const float* a0p = &Arow[(b0 + 0) * LDB];
    const float* a1p = &Arow[(b0 + 1) * LDB];
    const float* wp  = &Wre[jg * 4];

    for (int t = 0; t < TSTEPS; ++t) {
        for (int e = tid; e < (TB * HID) / 4; e += THREADS) {  // stage g_out0 slice
            int b = e >> 5, q = e & 31;
            *reinterpret_cast<float4*>(&Arow[b * LDB + q * 4]) =
                *reinterpret_cast<const float4*>(
                    &g_out0[((size_t)t * BATCH + B0 + b) * HID + q * 4]);
        }
        __syncthreads();

        u64 acc[2][8];
        #pragma unroll
        for (int jp = 0; jp < 8; ++jp) {
            u64 bb = pack_pair(b1s[j0 + 2*jp], b1s[j0 + 2*jp + 1]);
            acc[0][jp] = bb; acc[1][jp] = bb;
        }
        GEMM_LOOP(KB)
        __syncthreads();

        #pragma unroll
        for (int bi = 0; bi < 2; ++bi) {
            float v[16];
            #pragma unroll
            for (int jp = 0; jp < 8; ++jp) {
                v[2*jp]   = fast_tanh(lo2(acc[bi][jp]));
                v[2*jp+1] = fast_tanh(hi2(acc[bi][jp]));
            }
            float* dA = &Arow[(b0 + bi) * LDB + HID + j0];
            #pragma unroll
            for (int m = 0; m < 4; ++m)
                *reinterpret_cast<float4*>(dA + 4*m) =
                    make_float4(v[4*m], v[4*m+1], v[4*m+2], v[4*m+3]);
        }
    }
    __syncthreads();   // final h1 visible to all

    // FC head: 640 outputs over 256 threads
    for (int o = tid; o < TB * 10; o += THREADS) {
        int b = o / 10, c = o - b * 10;
        const float* hv = &Arow[b * LDB + HID];
        const float* wv = &fcs[c * HID];
        float s = fcbs[c];
        #pragma unroll 8
        for (int k = 0; k < HID; ++k) s = fmaf(hv[k], wv[k], s);
        out[(size_t)(B0 + b) * 10 + c] = s;
    }
}

extern "C" void kernel_launch(void* const* d_in, const int* in_sizes, int n_in,
                              void* d_out, int out_size) {
    const float* x     = (const float*)d_in[0];
    const float* Wih0  = (const float*)d_in[1];
    const float* Whh0  = (const float*)d_in[2];
    const float* bih0  = (const float*)d_in[3];
    const float* bhh0  = (const float*)d_in[4];
    const float* Wih1  = (const float*)d_in[5];
    const float* Whh1  = (const float*)d_in[6];
    const float* bih1  = (const float*)d_in[7];
    const float* bhh1  = (const float*)d_in[8];
    const float* fcw   = (const float*)d_in[9];
    const float* fcb   = (const float*)d_in[10];
    float* out = (float*)d_out;

    const int smemA = (KA * HID + TB * LDA + HID) * 4;                     // ~122 KB
    const int smemB = (KB * HID + TB * LDB + HID + 10 * HID + 16) * 4;     // ~203 KB
    cudaFuncSetAttribute(rnn_layer0,    cudaFuncAttributeMaxDynamicSharedMemorySize, smemA);
    cudaFuncSetAttribute(rnn_layer1_fc, cudaFuncAttributeMaxDynamicSharedMemorySize, smemB);

    const int grid = BATCH / TB;   // 128
    rnn_layer0<<<grid, THREADS, smemA>>>(x, Wih0, Whh0, bih0, bhh0);
    rnn_layer1_fc<<<grid, THREADS, smemB>>>(Wih1, Whh1, bih1, bhh1, fcw, fcb, out);
}

// round 11
// speedup vs baseline: 1.4517x; 1.4517x over previous
#include <cuda_runtime.h>
#include <cstdint>

#define TB      64
#define THREADS 256
#define HID     128
#define TSTEPS  28
#define INP     28
#define BATCH   8192
#define KA      156     // INP+HID concat k (layer 0)
#define KB      256     // HID+HID concat k (layer 1)
#define TBP     66      // Ak row pad (even -> 8B-aligned rows; ≡2 mod 32 -> conflict-free)

// layer-0 output sequence, [t][b][h]
__device__ __align__(16) float g_out0[(size_t)TSTEPS * BATCH * HID];

typedef unsigned long long u64;

__device__ __forceinline__ u64 pack_dup(float a) {
    u64 r; asm("mov.b64 %0, {%1, %1};" : "=l"(r) : "r"(__float_as_uint(a))); return r;
}
__device__ __forceinline__ u64 pack_pair(float lo, float hi) {
    u64 r; asm("mov.b64 %0, {%1, %2};" : "=l"(r) : "r"(__float_as_uint(lo)), "r"(__float_as_uint(hi))); return r;
}
__device__ __forceinline__ void ffma2(u64& d, u64 a, u64 b) {
    asm("fma.rn.f32x2 %0, %1, %2, %0;" : "+l"(d) : "l"(a), "l"(b));
}
__device__ __forceinline__ float lo2(u64 v) { return __uint_as_float((unsigned)v); }
__device__ __forceinline__ float hi2(u64 v) { return __uint_as_float((unsigned)(v >> 32)); }

__device__ __forceinline__ float fast_tanh(float x) {
    float e = __expf(2.0f * x);
    return 1.0f - __fdividef(2.0f, e + 1.0f);
}

extern __shared__ float smem[];

// per-k inner step: 1 LDS.64 (A pair) + 4 uniform LDS.128 (w) + 16 FFMA2
#define GEMM_LOOP(KK)                                                           \
    _Pragma("unroll 4")                                                         \
    for (int k = 0; k < KK; ++k) {                                              \
        u64 ap = *reinterpret_cast<const u64*>(akp); akp += TBP;                \
        u64 A0 = pack_dup(lo2(ap));                                             \
        u64 A1 = pack_dup(hi2(ap));                                             \
        ulonglong2 w0 = *reinterpret_cast<const ulonglong2*>(wkp);              \
        ulonglong2 w1 = *reinterpret_cast<const ulonglong2*>(wkp + 4);          \
        ulonglong2 w2 = *reinterpret_cast<const ulonglong2*>(wkp + 8);          \
        ulonglong2 w3 = *reinterpret_cast<const ulonglong2*>(wkp + 12);         \
        wkp += HID;                                                             \
        ffma2(acc[0][0], A0, w0.x); ffma2(acc[0][1], A0, w0.y);                 \
        ffma2(acc[0][2], A0, w1.x); ffma2(acc[0][3], A0, w1.y);                 \
        ffma2(acc[0][4], A0, w2.x); ffma2(acc[0][5], A0, w2.y);                 \
        ffma2(acc[0][6], A0, w3.x); ffma2(acc[0][7], A0, w3.y);                 \
        ffma2(acc[1][0], A1, w0.x); ffma2(acc[1][1], A1, w0.y);                 \
        ffma2(acc[1][2], A1, w1.x); ffma2(acc[1][3], A1, w1.y);                 \
        ffma2(acc[1][4], A1, w2.x); ffma2(acc[1][5], A1, w2.y);                 \
        ffma2(acc[1][6], A1, w3.x); ffma2(acc[1][7], A1, w3.y);                 \
    }

// ---------------- layer 0: full sequence -> g_out0 ----------------
__global__ void __launch_bounds__(THREADS, 1)
rnn_layer0(const float* __restrict__ x,
           const float* __restrict__ Wih0, const float* __restrict__ Whh0,
           const float* __restrict__ bih0, const float* __restrict__ bhh0)
{
    float* Wsm = smem;                 // [KA][HID] transposed weights
    float* Ak  = Wsm + KA * HID;       // [KA][TBP]: rows 0..27 = x_t, 28..155 = h
    float* b0s = Ak + KA * TBP;        // HID

    const int tid = threadIdx.x;
    const int B0  = blockIdx.x * TB;

    for (int d = tid; d < KA * HID; d += THREADS) {
        int k = d >> 7, j = d & 127;
        Wsm[k * HID + j] = (k < INP) ? Wih0[j * INP + k] : Whh0[j * HID + (k - INP)];
    }
    for (int j = tid; j < HID; j += THREADS) b0s[j] = bih0[j] + bhh0[j];
    for (int d = tid; d < HID * TB; d += THREADS)       // h0 = 0
        Ak[(INP + (d >> 6)) * TBP + (d & 63)] = 0.0f;
    __syncthreads();

    const int wid = tid >> 5, lane = tid & 31;
    const int j0 = wid * 16;
    const float* wbase = Wsm + j0;
    const float* abase = Ak + 2 * lane;

    for (int t = 0; t < TSTEPS; ++t) {
        // stage x[:,t,:] -> Ak[i][b]  (lanes = i, coalesced-ish global reads)
        for (int d = tid; d < TB * 32; d += THREADS) {
            int i = d & 31, b = d >> 5;
            if (i < INP)
                Ak[i * TBP + b] = x[(size_t)(B0 + b) * (TSTEPS * INP) + t * INP + i];
        }
        __syncthreads();   // stage + prev-step h visible

        u64 acc[2][8];
        #pragma unroll
        for (int jp = 0; jp < 8; ++jp) {
            u64 bb = pack_pair(b0s[j0 + 2*jp], b0s[j0 + 2*jp + 1]);
            acc[0][jp] = bb; acc[1][jp] = bb;
        }
        const float* akp = abase;
        const float* wkp = wbase;
        GEMM_LOOP(KA)
        __syncthreads();   // all h reads done before overwrite

        // epilogue: tanh, STS.64 (b-pair) into h rows of Ak
        #pragma unroll
        for (int jp = 0; jp < 8; ++jp) {
            float v00 = fast_tanh(lo2(acc[0][jp]));   // b0, j=2jp
            float v01 = fast_tanh(hi2(acc[0][jp]));   // b0, j=2jp+1
            float v10 = fast_tanh(lo2(acc[1][jp]));   // b1
            float v11 = fast_tanh(hi2(acc[1][jp]));
            int j = j0 + 2 * jp;
            *reinterpret_cast<u64*>(&Ak[(INP + j)     * TBP + 2*lane]) = pack_pair(v00, v10);
            *reinterpret_cast<u64*>(&Ak[(INP + j + 1) * TBP + 2*lane]) = pack_pair(v01, v11);
        }
        __syncthreads();   // h fully staged before cooperative writeout

        // writeout h(t) -> g_out0[t][b][:]  (lanes = b, conflict-free LDS)
        #pragma unroll
        for (int h2 = 0; h2 < 2; ++h2) {
            int b = lane + 32 * h2;
            float* dst = &g_out0[((size_t)t * BATCH + B0 + b) * HID];
            #pragma unroll
            for (int qq = 0; qq < 4; ++qq) {
                int q = wid * 4 + qq;
                float4 f;
                f.x = Ak[(INP + 4*q + 0) * TBP + b];
                f.y = Ak[(INP + 4*q + 1) * TBP + b];
                f.z = Ak[(INP + 4*q + 2) * TBP + b];
                f.w = Ak[(INP + 4*q + 3) * TBP + b];
                *reinterpret_cast<float4*>(dst + 4 * q) = f;
            }
        }
        // next iteration's pre-GEMM sync orders everything
    }
}

// ---------------- layer 1 + FC head ----------------
__global__ void __launch_bounds__(THREADS, 1)
rnn_layer1_fc(const float* __restrict__ Wih1, const float* __restrict__ Whh1,
              const float* __restrict__ bih1, const float* __restrict__ bhh1,
              const float* __restrict__ fcw,  const float* __restrict__ fcb,
              float* __restrict__ out)
{
    float* Wsm  = smem;                 // [KB][HID]
    float* Ak   = Wsm + KB * HID;       // [KB][TBP]: rows 0..127 = in0, 128..255 = h1
    float* b1s  = Ak + KB * TBP;        // HID
    float* fcs  = b1s + HID;            // 10*HID
    float* fcbs = fcs + 10 * HID;       // 16

    const int tid = threadIdx.x;
    const int B0  = blockIdx.x * TB;

    for (int d = tid; d < KB * HID; d += THREADS) {
        int k = d >> 7, j = d & 127;
        Wsm[k * HID + j] = (k < HID) ? Wih1[j * HID + k] : Whh1[j * HID + (k - HID)];
    }
    for (int j = tid; j < HID; j += THREADS) b1s[j] = bih1[j] + bhh1[j];
    for (int d = tid; d < 10 * HID; d += THREADS) fcs[d] = fcw[d];
    if (tid < 10) fcbs[tid] = fcb[tid];
    for (int d = tid; d < HID * TB; d += THREADS)      // h0 = 0
        Ak[(HID + (d >> 6)) * TBP + (d & 63)] = 0.0f;
    __syncthreads();

    const int wid = tid >> 5, lane = tid & 31;
    const int j0 = wid * 16;
    const float* wbase = Wsm + j0;
    const float* abase = Ak + 2 * lane;

    for (int t = 0; t < TSTEPS; ++t) {
        // stage in0(t): g_out0[t][b][:] -> Ak[k][b]  (lanes = b, conflict-free STS)
        #pragma unroll
        for (int h2 = 0; h2 < 2; ++h2) {
            int b = lane + 32 * h2;
            const float* src = &g_out0[((size_t)t * BATCH + B0 + b) * HID];
            #pragma unroll
            for (int qq = 0; qq < 4; ++qq) {
                int q = wid * 4 + qq;
                float4 f = *reinterpret_cast<const float4*>(src + 4 * q);
                Ak[(4*q + 0) * TBP + b] = f.x;
                Ak[(4*q + 1) * TBP + b] = f.y;
                Ak[(4*q + 2) * TBP + b] = f.z;
                Ak[(4*q + 3) * TBP + b] = f.w;
            }
        }
        __syncthreads();

        u64 acc[2][8];
        #pragma unroll
        for (int jp = 0; jp < 8; ++jp) {
            u64 bb = pack_pair(b1s[j0 + 2*jp], b1s[j0 + 2*jp + 1]);
            acc[0][jp] = bb; acc[1][jp] = bb;
        }
        const float* akp = abase;
        const float* wkp = wbase;
        GEMM_LOOP(KB)
        __syncthreads();

        #pragma unroll
        for (int jp = 0; jp < 8; ++jp) {
            float v00 = fast_tanh(lo2(acc[0][jp]));
            float v01 = fast_tanh(hi2(acc[0][jp]));
            float v10 = fast_tanh(lo2(acc[1][jp]));
            float v11 = fast_tanh(hi2(acc[1][jp]));
            int j = j0 + 2 * jp;
            *reinterpret_cast<u64*>(&Ak[(HID + j)     * TBP + 2*lane]) = pack_pair(v00, v10);
            *reinterpret_cast<u64*>(&Ak[(HID + j + 1) * TBP + 2*lane]) = pack_pair(v01, v11);
        }
        // next iteration's pre-GEMM sync publishes h(t)
    }
    __syncthreads();   // final h1 visible to all

    // FC head: 640 outputs
    for (int o = tid; o < TB * 10; o += THREADS) {
        int b = o / 10, c = o - b * 10;
        const float* wv = &fcs[c * HID];
        float s = fcbs[c];
        #pragma unroll 8
        for (int k = 0; k < HID; ++k)
            s = fmaf(Ak[(HID + k) * TBP + b], wv[k], s);
        out[(size_t)(B0 + b) * 10 + c] = s;
    }
}

extern "C" void kernel_launch(void* const* d_in, const int* in_sizes, int n_in,
                              void* d_out, int out_size) {
    const float* x     = (const float*)d_in[0];
    const float* Wih0  = (const float*)d_in[1];
    const float* Whh0  = (const float*)d_in[2];
    const float* bih0  = (const float*)d_in[3];
    const float* bhh0  = (const float*)d_in[4];
    const float* Wih1  = (const float*)d_in[5];
    const float* Whh1  = (const float*)d_in[6];
    const float* bih1  = (const float*)d_in[7];
    const float* bhh1  = (const float*)d_in[8];
    const float* fcw   = (const float*)d_in[9];
    const float* fcb   = (const float*)d_in[10];
    float* out = (float*)d_out;

    const int smemA = (KA * HID + KA * TBP + HID) * 4;                       // ~119 KB
    const int smemB = (KB * HID + KB * TBP + HID + 10 * HID + 16) * 4;       // ~200 KB
    cudaFuncSetAttribute(rnn_layer0,    cudaFuncAttributeMaxDynamicSharedMemorySize, smemA);
    cudaFuncSetAttribute(rnn_layer1_fc, cudaFuncAttributeMaxDynamicSharedMemorySize, smemB);

    const int grid = BATCH / TB;   // 128
    rnn_layer0<<<grid, THREADS, smemA>>>(x, Wih0, Whh0, bih0, bhh0);
    rnn_layer1_fc<<<grid, THREADS, smemB>>>(Wih1, Whh1, bih1, bhh1, fcw, fcb, out);
}